// round 15
// baseline (speedup 1.0000x reference)
#include <cuda_runtime.h>
#include <cuda_fp16.h>
#include <cstdint>

// Problem constants (fixed by the dataset)
#define PN0   200000
#define PN1   50000
#define PN2   10000
#define INF_  602
#define HID_  128
#define CLS_  41
#define FAN_  25

// GEMM tiling (fp16 m16n8k16, B fully smem-resident)
#define KP_    640          // K padded to multiple of 64 (10 chunks)
#define NCH_   10
#define KCH_   64
#define MT_    128          // rows per block
#define ASTRH  72           // A smem row stride (halfs): conflict-free LDSM
#define BSTRH  648          // B smem row stride (halfs): 648*2B -> rows 4 banks apart

#define BS_BYTES  (HID_ * BSTRH * 2)          // 165,888
#define AS_BYTES  (2 * MT_ * ASTRH * 2)       //  36,864
#define DYN_TOTAL (BS_BYTES + AS_BYTES)       // 202,752  (< 227 KB opt-in)

// agg kernel smem strides (floats; pad kills bank conflicts; %4==0 for float4)
#define W2STR  132
#define AGSTR  132

// Device scratch (no allocations allowed). 16B-aligned for vector access.
__device__ __align__(16) unsigned g_h1h[(size_t)PN1 * (HID_/2)];   // h1 fp16 packed (12.8 MB)

// int64 (nonneg, < 2^31) => every odd 32-bit word is 0.
__device__ __forceinline__ int sniff64(const int* w) {
    int f = 1;
    #pragma unroll
    for (int i = 1; i < 64; i += 2)
        if (w[i] != 0) f = 0;
    return f;
}

// ---------------------------------------------------------------------------
// Kernel 1: h1[j] = relu(features[map1[j]] @ W1^T + b1), fp16 mma.sync.
// 512 threads (16 warps) -> 128 rows x 128 cols; warp tile m16 x n64.
// B (all of W1, fp16, K-padded) converted once per block into resident smem;
// A ping-pong staged per 64-k chunk with register prefetch; one sync/chunk.
// Feature gather via float2 (row base only 8B-aligned: 602*4 % 16 == 8).
// ---------------------------------------------------------------------------
__global__ __launch_bounds__(512) void h1_kernel(
    const float* __restrict__ feat,
    const float* __restrict__ W1,
    const float* __restrict__ bias1,
    const void*  __restrict__ map1_raw)
{
    extern __shared__ __align__(16) char dyn[];
    __half* Bs = (__half*)dyn;                       // [128][648]
    __half* As = (__half*)(dyn + BS_BYTES);          // [2][128][72]
    __shared__ int   rows[MT_];
    __shared__ float b1s[HID_];
    __shared__ int   is64s;

    const int tid = threadIdx.x;
    const int r0  = blockIdx.x * MT_;

    if (tid == 0) is64s = sniff64((const int*)map1_raw);
    __syncthreads();

    if (tid < MT_) {
        int j = r0 + tid;
        int g = -1;
        if (j < PN1) {
            if (is64s) g = (int)((const long long*)map1_raw)[j];
            else       g = ((const int*)map1_raw)[j];
        }
        rows[tid] = g;
    }
    if (tid < HID_) b1s[tid] = bias1[tid];
    __syncthreads();

    const int warp = tid >> 5;
    const int lane = tid & 31;
    const int grp  = lane >> 2;          // 0..7
    const int qid  = lane & 3;           // 0..3
    const int m0   = (warp >> 1) * 16;   // 0..112
    const int n0   = (warp & 1) * 64;    // 0,64

    float d[8][4];
    #pragma unroll
    for (int t = 0; t < 8; t++)
        #pragma unroll
        for (int r = 0; r < 4; r++) d[t][r] = 0.f;

    // A staging: 4 threads per row, each covers 16 consecutive k of the chunk.
    const int arow = tid >> 2;           // 0..127
    const int aq   = tid & 3;
    const int gi   = rows[arow];
    const float* fp = feat + (size_t)(gi < 0 ? 0 : gi) * INF_;

    float2 pa[8];
    auto load_A = [&](int k0c) {
        #pragma unroll
        for (int i = 0; i < 8; i++) {
            int k = k0c + aq * 16 + 2 * i;       // even; never straddles (INF_ even)
            float2 v = make_float2(0.f, 0.f);
            if (gi >= 0 && k < INF_)
                v = *(const float2*)(fp + k);
            pa[i] = v;
        }
    };
    auto store_A = [&](int p) {
        __half2 h[8];
        #pragma unroll
        for (int i = 0; i < 8; i++)
            h[i] = __floats2half2_rn(pa[i].x, pa[i].y);
        __half* dst = As + p * (MT_ * ASTRH) + arow * ASTRH + aq * 16;
        *(uint4*)dst       = *(uint4*)&h[0];
        *(uint4*)(dst + 8) = *(uint4*)&h[4];
    };

    // Issue chunk-0 A gather (DRAM) first so its latency hides the B convert.
    load_A(0);

    // ---- B: one-time fp32->fp16 convert of W1 into resident smem ----
    // 4 threads per n row, segments of 162 k (covers 0..647; k>=602 -> 0).
    {
        const int brow = tid >> 2;
        const int bq   = tid & 3;
        const float* wrow = W1 + brow * INF_;
        #pragma unroll 9
        for (int j = 0; j < 81; j++) {
            int k = bq * 162 + 2 * j;
            __half2 h = __float2half2_rn(0.f);
            if (k <= 600) {                      // float2 within row, 8B-aligned
                float2 v = *(const float2*)(wrow + k);
                h = __floats2half2_rn(v.x, v.y);
            }
            *(__half2*)&Bs[brow * BSTRH + k] = h;
        }
    }

    store_A(0);

    // LDSM lane-offsets (chunk-invariant).
    const int a_r = m0 + (lane & 7) + 8 * ((lane >> 3) & 1);
    const int a_c = 8 * (lane >> 4);
    uint32_t a_base[2];
    #pragma unroll
    for (int p = 0; p < 2; p++)
        a_base[p] = (uint32_t)__cvta_generic_to_shared(
            As + p * (MT_ * ASTRH) + a_r * ASTRH + a_c);
    // B x4 (rows=n, cols=k): regs b0..b3 = n[0:8)k[0:8), n[0:8)k[8:16),
    //                                      n[8:16)k[0:8), n[8:16)k[8:16).
    const int b_row = n0 + (lane & 7) + 8 * ((lane >> 4) & 1);
    const int b_kof = 8 * ((lane >> 3) & 1);
    const uint32_t b_base = (uint32_t)__cvta_generic_to_shared(
        Bs + b_row * BSTRH + b_kof);

    for (int c = 0; c < NCH_; c++) {
        const int p = c & 1;
        __syncthreads();                 // publish A[p] (+ B on first iter)
        if (c + 1 < NCH_)
            load_A((c + 1) * KCH_);

        #pragma unroll
        for (int ks = 0; ks < KCH_; ks += 16) {
            uint32_t a0, a1, a2, a3;
            asm volatile(
                "ldmatrix.sync.aligned.m8n8.x4.shared.b16 {%0,%1,%2,%3}, [%4];\n"
                : "=r"(a0), "=r"(a1), "=r"(a2), "=r"(a3)
                : "r"(a_base[p] + (uint32_t)(ks * 2)));
            #pragma unroll
            for (int nb = 0; nb < 4; nb++) {
                uint32_t b0, b1, b2, b3;
                asm volatile(
                    "ldmatrix.sync.aligned.m8n8.x4.shared.b16 {%0,%1,%2,%3}, [%4];\n"
                    : "=r"(b0), "=r"(b1), "=r"(b2), "=r"(b3)
                    : "r"(b_base + (uint32_t)((16 * nb * BSTRH + c * KCH_ + ks) * 2)));
                int t0 = 2 * nb, t1 = 2 * nb + 1;
                asm volatile(
                    "mma.sync.aligned.m16n8k16.row.col.f32.f16.f16.f32 "
                    "{%0,%1,%2,%3}, {%4,%5,%6,%7}, {%8,%9}, {%0,%1,%2,%3};\n"
                    : "+f"(d[t0][0]), "+f"(d[t0][1]), "+f"(d[t0][2]), "+f"(d[t0][3])
                    : "r"(a0), "r"(a1), "r"(a2), "r"(a3), "r"(b0), "r"(b1));
                asm volatile(
                    "mma.sync.aligned.m16n8k16.row.col.f32.f16.f16.f32 "
                    "{%0,%1,%2,%3}, {%4,%5,%6,%7}, {%8,%9}, {%0,%1,%2,%3};\n"
                    : "+f"(d[t1][0]), "+f"(d[t1][1]), "+f"(d[t1][2]), "+f"(d[t1][3])
                    : "r"(a0), "r"(a1), "r"(a2), "r"(a3), "r"(b2), "r"(b3));
            }
        }

        if (c + 1 < NCH_)
            store_A(p ^ 1);              // WAR vs iter c-1 reads separated by sync
    }

    // ---- epilogue: bias + relu, fp16 pack, write h1 ----
    const int row_a = r0 + m0 + grp;
    const int row_b = row_a + 8;
    #pragma unroll
    for (int t = 0; t < 8; t++) {
        int c0 = n0 + 8 * t + 2 * qid;      // even
        float bx = b1s[c0], by = b1s[c0 + 1];
        if (row_a < PN1) {
            __half2 v = __floats2half2_rn(fmaxf(d[t][0] + bx, 0.f),
                                          fmaxf(d[t][1] + by, 0.f));
            g_h1h[(size_t)row_a * (HID_/2) + (c0 >> 1)] = *(unsigned*)&v;
        }
        if (row_b < PN1) {
            __half2 v = __floats2half2_rn(fmaxf(d[t][2] + bx, 0.f),
                                          fmaxf(d[t][3] + by, 0.f));
            g_h1h[(size_t)row_b * (HID_/2) + (c0 >> 1)] = *(unsigned*)&v;
        }
    }
}

// ---------------------------------------------------------------------------
// Kernel 2: agg + classify, shuffle-free.
// 256 threads, 8 seeds per block (grid 1250). Warp w gathers+means seed w's
// neighbors (uint2 fp16 loads, h1 L2-resident) into smem; 328 (seed,class)
// outputs as float4 dot products from smem (W2 staged, stride-132 pad).
// ---------------------------------------------------------------------------
__global__ __launch_bounds__(256) void agg_kernel(
    const void*  __restrict__ neigh_raw,
    const float* __restrict__ W2,
    const float* __restrict__ b2,
    float*       __restrict__ out)
{
    __shared__ float W2s[CLS_ * W2STR];
    __shared__ float aggS[8 * AGSTR];
    __shared__ float b2s[CLS_];
    __shared__ int   idxs[8][32];
    __shared__ int   is64s;

    const int t    = threadIdx.x;
    const int w    = t >> 5;
    const int lane = t & 31;
    const int seed0 = blockIdx.x * 8;

    if (t == 0) is64s = sniff64((const int*)neigh_raw);
    __syncthreads();

    for (int i = t; i < CLS_ * HID_; i += 256) {
        int c = i >> 7, k = i & 127;
        W2s[c * W2STR + k] = W2[i];
    }
    if (t < CLS_) b2s[t] = b2[t];

    if (lane < FAN_) {
        long long v;
        if (is64s) v = ((const long long*)neigh_raw)[(size_t)(seed0 + w) * FAN_ + lane];
        else       v = (long long)((const int*)neigh_raw)[(seed0 + w) * FAN_ + lane];
        idxs[w][lane] = (int)v;
    }
    __syncwarp();

    float a0 = 0.f, a1 = 0.f, a2 = 0.f, a3 = 0.f;
    #pragma unroll
    for (int f = 0; f < FAN_; f++) {
        int r = idxs[w][f];
        uint2 v = *(const uint2*)&g_h1h[(size_t)r * (HID_/2) + 2 * lane];
        float2 flo = __half22float2(*(__half2*)&v.x);
        float2 fhi = __half22float2(*(__half2*)&v.y);
        a0 += flo.x; a1 += flo.y; a2 += fhi.x; a3 += fhi.y;
    }
    const float inv = 1.0f / (float)FAN_;
    *(float4*)&aggS[w * AGSTR + 4 * lane] =
        make_float4(a0 * inv, a1 * inv, a2 * inv, a3 * inv);
    __syncthreads();

    for (int o = t; o < 8 * CLS_; o += 256) {
        int s = o / CLS_;
        int c = o - s * CLS_;
        const float4* wr = (const float4*)&W2s[c * W2STR];
        const float4* ar = (const float4*)&aggS[s * AGSTR];
        float acc = 0.f;
        #pragma unroll
        for (int k = 0; k < HID_ / 4; k++) {
            float4 wv = wr[k];
            float4 av = ar[k];
            acc += wv.x * av.x + wv.y * av.y + wv.z * av.z + wv.w * av.w;
        }
        out[(seed0 + s) * CLS_ + c] = acc + b2s[c];
    }
}

// ---------------------------------------------------------------------------
extern "C" void kernel_launch(void* const* d_in, const int* in_sizes, int n_in,
                              void* d_out, int out_size) {
    const float* feat  = (const float*)d_in[0];   // [200000, 602]
    const float* W1    = (const float*)d_in[1];   // [128, 602]
    const float* b1    = (const float*)d_in[2];   // [128]
    const float* W2    = (const float*)d_in[3];   // [41, 128]
    const float* b2    = (const float*)d_in[4];   // [41]
    const void*  map1  = d_in[5];                 // [50000] int32/int64 (runtime-detected)
    const void*  neigh = d_in[6];                 // [10000, 25] int32/int64
    float* out = (float*)d_out;                   // [10000, 41]

    static int smem_set = 0;
    if (!smem_set) {
        cudaFuncSetAttribute(h1_kernel, cudaFuncAttributeMaxDynamicSharedMemorySize,
                             DYN_TOTAL);
        smem_set = 1;
    }

    h1_kernel<<<(PN1 + MT_ - 1) / MT_, 512, DYN_TOTAL>>>(feat, W1, b1, map1);
    agg_kernel<<<PN2 / 8, 256>>>(neigh, W2, b2, out);
}